// round 15
// baseline (speedup 1.0000x reference)
#include <cuda_runtime.h>
#include <cuda_bf16.h>
#include <math.h>
#include <stdint.h>

#define BATCH   4
#define LSEQ    2048
#define DMODEL  512
#define DINNER  1024
#define DSTATE  16
#define DTRANK  32
#define NROWS   (BATCH * LSEQ)         // 8192
#define XPROJN  (DTRANK + 2 * DSTATE)  // 64
#define NC      64                     // scan chunks
#define LC      32                     // steps per chunk

// ---------------- scratch (static device globals: no allocs allowed) --------
__device__ float g_xz  [NROWS * 2 * DINNER];    // [u_raw | z]
__device__ float g_u   [NROWS * DINNER];        // silu(conv(u)+b)
__device__ float g_xdbl[NROWS * XPROJN];        // [dt_r | B | C] (dtr cols unused)
__device__ float g_dt  [NROWS * DINNER];        // softplus(dt)
__device__ float g_yo  [NROWS * DMODEL];        // y @ W_out
__device__ float g_S    [NC * BATCH * DINNER * DSTATE];  // chunk end states
__device__ float g_Hini [NC * BATCH * DINNER * DSTATE];  // chunk init states
__device__ float g_dts  [NC * BATCH * DINNER];           // chunk dt sums

// bf16 split operands for tensor-core GEMMs
__device__ __nv_bfloat16 gA1h[NROWS * DMODEL],  gA1l[NROWS * DMODEL];   // LN1 out
__device__ __nv_bfloat16 gA2h[NROWS * DINNER],  gA2l[NROWS * DINNER];   // scan out
__device__ __nv_bfloat16 gW1h[2 * DINNER * DMODEL], gW1l[2 * DINNER * DMODEL]; // W_in^T  [2048][512]
__device__ __nv_bfloat16 gW2h[DMODEL * DINNER],     gW2l[DMODEL * DINNER];     // W_out^T [512][1024]

// ---------------- helpers ----------------------------------------------------
__device__ __forceinline__ uint32_t smem_u32(const void* p) {
    uint32_t a;
    asm("{ .reg .u64 t; cvta.to.shared.u64 t, %1; cvt.u32.u64 %0, t; }" : "=r"(a) : "l"(p));
    return a;
}
__device__ __forceinline__ void split_store(float v, __nv_bfloat16* h, __nv_bfloat16* l, size_t i) {
    __nv_bfloat16 hb = __float2bfloat16(v);
    h[i] = hb;
    l[i] = __float2bfloat16(v - __bfloat162float(hb));
}
__device__ __forceinline__ void ldsm4(uint32_t* r, uint32_t addr) {
    asm volatile("ldmatrix.sync.aligned.m8n8.x4.shared.b16 {%0,%1,%2,%3}, [%4];"
                 : "=r"(r[0]), "=r"(r[1]), "=r"(r[2]), "=r"(r[3]) : "r"(addr));
}
__device__ __forceinline__ void mma16816(float* c, const uint32_t* a, uint32_t b0, uint32_t b1) {
    asm volatile(
        "mma.sync.aligned.m16n8k16.row.col.f32.bf16.bf16.f32 "
        "{%0,%1,%2,%3}, {%4,%5,%6,%7}, {%8,%9}, {%0,%1,%2,%3};"
        : "+f"(c[0]), "+f"(c[1]), "+f"(c[2]), "+f"(c[3])
        : "r"(a[0]), "r"(a[1]), "r"(a[2]), "r"(a[3]), "r"(b0), "r"(b1));
}
__device__ __forceinline__ void cpasync16(uint32_t dst, const void* src) {
    asm volatile("cp.async.cg.shared.global [%0], [%1], 16;" :: "r"(dst), "l"(src));
}
__device__ __forceinline__ void cp_commit() { asm volatile("cp.async.commit_group;" ::: "memory"); }
__device__ __forceinline__ void cp_wait1()  { asm volatile("cp.async.wait_group 1;" ::: "memory"); }
__device__ __forceinline__ void cp_wait0()  { asm volatile("cp.async.wait_group 0;" ::: "memory"); }
// packed fp32x2
__device__ __forceinline__ unsigned long long pack2(float a) {
    unsigned long long r;
    asm("mov.b64 %0, {%1, %1};" : "=l"(r) : "f"(a));
    return r;
}
__device__ __forceinline__ void fma2(unsigned long long& d,
                                     unsigned long long a,
                                     unsigned long long b) {
    asm("fma.rn.f32x2 %0, %1, %2, %0;" : "+l"(d) : "l"(a), "l"(b));
}

// ---------------- layernorm ---------------------------------------------------
template<int MODE>
__global__ void ln_kernel(const float* __restrict__ x,
                          const float* __restrict__ w,
                          const float* __restrict__ b,
                          float* __restrict__ outp) {
    __shared__ float sbuf[4];
    int row = blockIdx.x;
    int tid = threadIdx.x;
    float4 v = reinterpret_cast<const float4*>(x + (size_t)row * DMODEL)[tid];
    if (MODE == 1) {
        float4 r = reinterpret_cast<const float4*>(g_yo + (size_t)row * DMODEL)[tid];
        v.x += r.x; v.y += r.y; v.z += r.z; v.w += r.w;
    }
    float s = v.x + v.y + v.z + v.w;
    #pragma unroll
    for (int o = 16; o > 0; o >>= 1) s += __shfl_xor_sync(0xffffffffu, s, o);
    if ((tid & 31) == 0) sbuf[tid >> 5] = s;
    __syncthreads();
    float mean = (sbuf[0] + sbuf[1] + sbuf[2] + sbuf[3]) * (1.0f / DMODEL);
    __syncthreads();
    float dx = v.x - mean, dy = v.y - mean, dz = v.z - mean, dw = v.w - mean;
    float sq = dx * dx + dy * dy + dz * dz + dw * dw;
    #pragma unroll
    for (int o = 16; o > 0; o >>= 1) sq += __shfl_xor_sync(0xffffffffu, sq, o);
    if ((tid & 31) == 0) sbuf[tid >> 5] = sq;
    __syncthreads();
    float var = (sbuf[0] + sbuf[1] + sbuf[2] + sbuf[3]) * (1.0f / DMODEL);
    float inv = rsqrtf(var + 1e-5f);
    float4 wv = reinterpret_cast<const float4*>(w)[tid];
    float4 bv = reinterpret_cast<const float4*>(b)[tid];
    float o0 = dx * inv * wv.x + bv.x;
    float o1 = dy * inv * wv.y + bv.y;
    float o2 = dz * inv * wv.z + bv.z;
    float o3 = dw * inv * wv.w + bv.w;
    if (MODE == 0) {
        size_t base = (size_t)row * DMODEL + tid * 4;
        split_store(o0, gA1h, gA1l, base + 0);
        split_store(o1, gA1h, gA1l, base + 1);
        split_store(o2, gA1h, gA1l, base + 2);
        split_store(o3, gA1h, gA1l, base + 3);
    } else {
        float4 o4; o4.x = o0; o4.y = o1; o4.z = o2; o4.w = o3;
        reinterpret_cast<float4*>(outp + (size_t)row * DMODEL)[tid] = o4;
    }
}

// ---------------- transpose + bf16 split for both weights (merged) ----------
__global__ void tsplit_all(const float* __restrict__ W_in,
                           const float* __restrict__ W_out) {
    int blk = blockIdx.x;
    int R, Cc, bx, by;
    const float* src;
    __nv_bfloat16 *dh, *dl;
    if (blk < 1024) {               // W_in [512][2048] -> [2048][512]
        R = DMODEL; Cc = 2 * DINNER; src = W_in; dh = gW1h; dl = gW1l;
        bx = blk & 63; by = blk >> 6;
    } else {                        // W_out [1024][512] -> [512][1024]
        int b2 = blk - 1024;
        R = DINNER; Cc = DMODEL; src = W_out; dh = gW2h; dl = gW2l;
        bx = b2 & 15; by = b2 >> 4;
    }
    __shared__ float t[32][33];
    int tx = threadIdx.x & 31, tq = threadIdx.x >> 5;
    #pragma unroll
    for (int j = 0; j < 32; j += 8)
        t[tq + j][tx] = src[(size_t)(by * 32 + tq + j) * Cc + bx * 32 + tx];
    __syncthreads();
    #pragma unroll
    for (int j = 0; j < 32; j += 8) {
        float v = t[tx][tq + j];
        size_t di = (size_t)(bx * 32 + tq + j) * R + by * 32 + tx;
        split_store(v, dh, dl, di);
    }
}

// ---------------- HMMA GEMM, BK=64, SW128, 2-stage cp.async (R7 proven) -----
#define STAGE_BYTES 65536
#define GEMM_SMEM   (2 * STAGE_BYTES)
template<int MODE>
__global__ __launch_bounds__(256)
void gemm_hmma() {
    constexpr int N = (MODE == 0) ? 2 * DINNER : DMODEL;
    constexpr int K = (MODE == 0) ? DMODEL : DINNER;
    constexpr int KT = K / 64;
    const __nv_bfloat16* Ah_g = (MODE == 0) ? gA1h : gA2h;
    const __nv_bfloat16* Al_g = (MODE == 0) ? gA1l : gA2l;
    const __nv_bfloat16* Bh_g = (MODE == 0) ? gW1h : gW2h;
    const __nv_bfloat16* Bl_g = (MODE == 0) ? gW1l : gW2l;
    float* C = (MODE == 0) ? g_xz : g_yo;

    extern __shared__ __align__(1024) char smem[];
    const uint32_t oAh = 0, oAl = 16384, oBh = 32768, oBl = 49152;
    uint32_t sb = smem_u32(smem);
    int tid = threadIdx.x, lane = tid & 31, wid = tid >> 5;
    int bx = blockIdx.x, by = blockIdx.y;
    int m0 = (wid >> 1) * 32;
    int n0 = (wid & 1) * 64;

    float c[2][8][4];
    #pragma unroll
    for (int i = 0; i < 2; i++)
        #pragma unroll
        for (int j = 0; j < 8; j++)
            #pragma unroll
            for (int q = 0; q < 4; q++) c[i][j][q] = 0.0f;

    auto issue = [&](int stage, int kt) {
        uint32_t s0 = sb + stage * STAGE_BYTES;
        #pragma unroll
        for (int i = 0; i < 4; i++) {
            int idx = tid + i * 256;
            int row = idx >> 3, c8 = idx & 7;
            size_t ga = (size_t)(by * 128 + row) * K + kt * 64 + c8 * 8;
            size_t gb = (size_t)(bx * 128 + row) * K + kt * 64 + c8 * 8;
            uint32_t off = row * 128 + c8 * 16;
            uint32_t sw = off ^ ((off >> 3) & 0x70);
            cpasync16(s0 + oAh + sw, Ah_g + ga);
            cpasync16(s0 + oAl + sw, Al_g + ga);
            cpasync16(s0 + oBh + sw, Bh_g + gb);
            cpasync16(s0 + oBl + sw, Bl_g + gb);
        }
        cp_commit();
    };

    issue(0, 0);
    for (int kt = 0; kt < KT; kt++) {
        int cur = kt & 1;
        if (kt + 1 < KT) { issue(cur ^ 1, kt + 1); cp_wait1(); }
        else             { cp_wait0(); }
        __syncthreads();
        uint32_t bb = sb + cur * STAGE_BYTES;
        #pragma unroll
        for (int ks = 0; ks < 4; ks++) {
            int r = lane & 15, chs = ks * 2 + (lane >> 4);
            uint32_t ah[2][4], al[2][4];
            #pragma unroll
            for (int mi = 0; mi < 2; mi++) {
                uint32_t off = (m0 + mi * 16 + r) * 128 + chs * 16;
                uint32_t sw = off ^ ((off >> 3) & 0x70);
                ldsm4(ah[mi], bb + oAh + sw);
                ldsm4(al[mi], bb + oAl + sw);
            }
            #pragma unroll
            for (int nq = 0; nq < 4; nq++) {
                uint32_t off = (n0 + nq * 16 + r) * 128 + chs * 16;
                uint32_t sw = off ^ ((off >> 3) & 0x70);
                uint32_t bh[4], bl[4];
                ldsm4(bh, bb + oBh + sw);
                ldsm4(bl, bb + oBl + sw);
                #pragma unroll
                for (int mi = 0; mi < 2; mi++) {
                    #pragma unroll
                    for (int sub = 0; sub < 2; sub++) {
                        float* cc = c[mi][nq * 2 + sub];
                        uint32_t b0 = sub ? bh[1] : bh[0];
                        uint32_t b1 = sub ? bh[3] : bh[2];
                        mma16816(cc, ah[mi], b0, b1);
                        mma16816(cc, al[mi], b0, b1);
                        uint32_t l0 = sub ? bl[1] : bl[0];
                        uint32_t l1 = sub ? bl[3] : bl[2];
                        mma16816(cc, ah[mi], l0, l1);
                    }
                }
            }
        }
        __syncthreads();
    }

    int gid = lane >> 2, tig = lane & 3;
    #pragma unroll
    for (int mi = 0; mi < 2; mi++) {
        #pragma unroll
        for (int nb = 0; nb < 8; nb++) {
            float* p = C + (size_t)(by * 128 + m0 + mi * 16 + gid) * N
                         + bx * 128 + n0 + nb * 8 + 2 * tig;
            float2 v0; v0.x = c[mi][nb][0]; v0.y = c[mi][nb][1];
            float2 v1; v1.x = c[mi][nb][2]; v1.y = c[mi][nb][3];
            *reinterpret_cast<float2*>(p) = v0;
            *reinterpret_cast<float2*>(p + (size_t)8 * N) = v1;
        }
    }
}

// ---------------- FUSED: conv+silu -> xproj -> dtproj -----------------------
// One block per 32-row tile (256 blocks). u tile lives in smem; eliminates the
// g_u re-read by xproj and the g_xdbl round-trip for dtproj.
// smem: su[32*1024] | Bs[32][64] | dtr[32][33]
#define FUSED_SMEM ((32 * 1024 + 32 * 64 + 32 * 33) * 4)
__global__ __launch_bounds__(256)
void fused_mid_kernel(const float* __restrict__ conv_w,
                      const float* __restrict__ conv_b,
                      const float* __restrict__ W_xprj,
                      const float* __restrict__ W_dt,
                      const float* __restrict__ b_dt) {
    extern __shared__ float sm[];
    float* su   = sm;                       // [32][1024]
    float* Bs   = sm + 32 * 1024;           // [32][64]
    float* dtrs = Bs + 32 * 64;             // [32][33]
    int tid = threadIdx.x;
    int r0 = blockIdx.x * 32;               // global row base (tiles don't cross batch)
    int l0 = r0 & (LSEQ - 1);

    // ---- phase 1: conv + silu -> su + g_u ----
    #pragma unroll
    for (int it = 0; it < 32; it++) {
        int wi = tid + it * 256;            // 0..8191
        int row = wi >> 8;                  // 0..31
        int e4 = (wi & 255) * 4;            // col group
        int l = l0 + row;
        size_t gbase = (size_t)(r0 + row) * 2 * DINNER + e4;
        float4 w0 = *reinterpret_cast<const float4*>(conv_w + (e4 + 0) * 4);
        float4 w1 = *reinterpret_cast<const float4*>(conv_w + (e4 + 1) * 4);
        float4 w2 = *reinterpret_cast<const float4*>(conv_w + (e4 + 2) * 4);
        float4 w3 = *reinterpret_cast<const float4*>(conv_w + (e4 + 3) * 4);
        float4 bb = *reinterpret_cast<const float4*>(conv_b + e4);
        float4 acc = bb;
        float4 xc = *reinterpret_cast<const float4*>(g_xz + gbase);
        acc.x += xc.x * w0.w; acc.y += xc.y * w1.w; acc.z += xc.z * w2.w; acc.w += xc.w * w3.w;
        if (l >= 1) {
            float4 x1 = *reinterpret_cast<const float4*>(g_xz + gbase - 2 * DINNER);
            acc.x += x1.x * w0.z; acc.y += x1.y * w1.z; acc.z += x1.z * w2.z; acc.w += x1.w * w3.z;
        }
        if (l >= 2) {
            float4 x2 = *reinterpret_cast<const float4*>(g_xz + gbase - 4 * DINNER);
            acc.x += x2.x * w0.y; acc.y += x2.y * w1.y; acc.z += x2.z * w2.y; acc.w += x2.w * w3.y;
        }
        if (l >= 3) {
            float4 x3 = *reinterpret_cast<const float4*>(g_xz + gbase - 6 * DINNER);
            acc.x += x3.x * w0.x; acc.y += x3.y * w1.x; acc.z += x3.z * w2.x; acc.w += x3.w * w3.x;
        }
        float4 uu;
        uu.x = acc.x / (1.0f + __expf(-acc.x));
        uu.y = acc.y / (1.0f + __expf(-acc.y));
        uu.z = acc.z / (1.0f + __expf(-acc.z));
        uu.w = acc.w / (1.0f + __expf(-acc.w));
        *reinterpret_cast<float4*>(su + row * 1024 + e4) = uu;
        *reinterpret_cast<float4*>(g_u + (size_t)(r0 + row) * DINNER + e4) = uu;
    }
    __syncthreads();

    // ---- phase 2: xproj (32x64 = su[32,1024] @ W_xprj[1024,64]) ----
    int ty = tid >> 4, tx = tid & 15;       // 16x16; rows ty, ty+16; cols tx*4
    unsigned long long acc2[2][2];
    acc2[0][0] = acc2[0][1] = acc2[1][0] = acc2[1][1] = 0ull;
    for (int k0 = 0; k0 < DINNER; k0 += 32) {
        // stage Bs[32][64]: 2048 floats / 256 thr = 2 float4 each
        #pragma unroll
        for (int j = 0; j < 2; j++) {
            int idx = (tid + j * 256) * 4;  // 0..8188 step4
            int br = idx >> 6, bc = idx & 63;
            *reinterpret_cast<float4*>(Bs + br * 64 + bc) =
                *reinterpret_cast<const float4*>(W_xprj + (size_t)(k0 + br) * XPROJN + bc);
        }
        __syncthreads();
        #pragma unroll 8
        for (int k = 0; k < 32; k++) {
            unsigned long long a0 = pack2(su[ty * 1024 + k0 + k]);
            unsigned long long a1 = pack2(su[(ty + 16) * 1024 + k0 + k]);
            ulonglong2 rb = *reinterpret_cast<const ulonglong2*>(Bs + k * 64 + tx * 4);
            fma2(acc2[0][0], a0, rb.x);
            fma2(acc2[0][1], a0, rb.y);
            fma2(acc2[1][0], a1, rb.x);
            fma2(acc2[1][1], a1, rb.y);
        }
        __syncthreads();
    }
    // distribute results: cols 0..31 -> dtrs (smem), cols 32..63 -> g_xdbl (B/C)
    #pragma unroll
    for (int rr = 0; rr < 2; rr++) {
        int row = ty + rr * 16;
        float2 v0 = *reinterpret_cast<float2*>(&acc2[rr][0]);
        float2 v1 = *reinterpret_cast<float2*>(&acc2[rr][1]);
        if (tx < 8) {
            dtrs[row * 33 + tx * 4 + 0] = v0.x;
            dtrs[row * 33 + tx * 4 + 1] = v0.y;
            dtrs[row * 33 + tx * 4 + 2] = v1.x;
            dtrs[row * 33 + tx * 4 + 3] = v1.y;
        } else {
            float4 o; o.x = v0.x; o.y = v0.y; o.z = v1.x; o.w = v1.y;
            *reinterpret_cast<float4*>(g_xdbl + (size_t)(r0 + row) * XPROJN + tx * 4) = o;
        }
    }
    __syncthreads();

    // ---- phase 3: dt = softplus(dtr @ W_dt + b_dt), 32 rows x 1024 cols ----
    #pragma unroll
    for (int rg = 0; rg < 4; rg++) {
        float acc[8][4];
        #pragma unroll
        for (int i = 0; i < 8; i++)
            #pragma unroll
            for (int j = 0; j < 4; j++) acc[i][j] = 0.0f;
        #pragma unroll 4
        for (int k = 0; k < DTRANK; k++) {
            float wv[4];
            #pragma unroll
            for (int j = 0; j < 4; j++) wv[j] = W_dt[(size_t)k * DINNER + tid + j * 256];
            #pragma unroll
            for (int i = 0; i < 8; i++) {
                float a = dtrs[(rg * 8 + i) * 33 + k];
                #pragma unroll
                for (int j = 0; j < 4; j++) acc[i][j] = fmaf(a, wv[j], acc[i][j]);
            }
        }
        #pragma unroll
        for (int j = 0; j < 4; j++) {
            int col = tid + j * 256;
            float bb = b_dt[col];
            #pragma unroll
            for (int i = 0; i < 8; i++) {
                float v = acc[i][j] + bb;
                float sp = (v > 20.0f) ? v : log1pf(__expf(v));
                g_dt[(size_t)(r0 + rg * 8 + i) * DINNER + col] = sp;
            }
        }
    }
}

// ---------------- chunked selective scan ------------------------------------
__global__ __launch_bounds__(128)
void scan1_kernel(const float* __restrict__ A_log) {
    __shared__ float dt_s[LC][128];
    __shared__ float u_s [LC][128];
    __shared__ float B_s [LC][DSTATE];
    int tid = threadIdx.x;
    int e = blockIdx.x * 128 + tid;
    int b = blockIdx.y, cch = blockIdx.z;
    int l0 = cch * LC;

    float Ar[DSTATE];
    #pragma unroll
    for (int n = 0; n < DSTATE; n++) Ar[n] = -__expf(A_log[e * DSTATE + n]);

    #pragma unroll
    for (int t = 0; t < LC; t++) {
        size_t row = (size_t)(b * LSEQ + l0 + t);
        dt_s[t][tid] = g_dt[row * DINNER + e];
        u_s [t][tid] = g_u [row * DINNER + e];
    }
    for (int idx = tid; idx < LC * DSTATE; idx += 128) {
        int t = idx >> 4, n = idx & 15;
        size_t row = (size_t)(b * LSEQ + l0 + t);
        B_s[t][n] = g_xdbl[row * XPROJN + DTRANK + n];
    }
    __syncthreads();

    float h[DSTATE];
    #pragma unroll
    for (int n = 0; n < DSTATE; n++) h[n] = 0.0f;
    float dts = 0.0f;
    #pragma unroll 4
    for (int t = 0; t < LC; t++) {
        float dt = dt_s[t][tid];
        dts += dt;
        float du = dt * u_s[t][tid];
        #pragma unroll
        for (int n = 0; n < DSTATE; n++) {
            float dA = __expf(dt * Ar[n]);
            h[n] = fmaf(dA, h[n], du * B_s[t][n]);
        }
    }
    size_t sbase = ((size_t)(cch * BATCH + b) * DINNER + e);
    float* Sp = g_S + sbase * DSTATE;
    #pragma unroll
    for (int n = 0; n < DSTATE; n += 4) {
        float4 v; v.x = h[n]; v.y = h[n + 1]; v.z = h[n + 2]; v.w = h[n + 3];
        *reinterpret_cast<float4*>(Sp + n) = v;
    }
    g_dts[sbase] = dts;
}

__global__ __launch_bounds__(256)
void scan2_kernel(const float* __restrict__ A_log) {
    int tid = threadIdx.x;
    int el = tid >> 4, n = tid & 15;
    int e = blockIdx.x * 16 + el;
    int b = blockIdx.y;
    float Ar = -__expf(A_log[e * DSTATE + n]);
    float h = 0.0f;
    #pragma unroll 4
    for (int cch = 0; cch < NC; cch++) {
        size_t sbase = ((size_t)(cch * BATCH + b) * DINNER + e);
        float dts = g_dts[sbase];
        g_Hini[sbase * DSTATE + n] = h;
        h = fmaf(__expf(Ar * dts), h, g_S[sbase * DSTATE + n]);
    }
}

__global__ __launch_bounds__(128)
void scan3_kernel(const float* __restrict__ A_log, const float* __restrict__ D_param) {
    __shared__ float dt_s[LC][128];
    __shared__ float u_s [LC][128];
    __shared__ float B_s [LC][DSTATE];
    __shared__ float C_s [LC][DSTATE];
    int tid = threadIdx.x;
    int e = blockIdx.x * 128 + tid;
    int b = blockIdx.y, cch = blockIdx.z;
    int l0 = cch * LC;

    float Ar[DSTATE];
    #pragma unroll
    for (int n = 0; n < DSTATE; n++) Ar[n] = -__expf(A_log[e * DSTATE + n]);
    float Dp = D_param[e];

    #pragma unroll
    for (int t = 0; t < LC; t++) {
        size_t row = (size_t)(b * LSEQ + l0 + t);
        dt_s[t][tid] = g_dt[row * DINNER + e];
        u_s [t][tid] = g_u [row * DINNER + e];
    }
    for (int idx = tid; idx < LC * DSTATE; idx += 128) {
        int t = idx >> 4, n = idx & 15;
        size_t row = (size_t)(b * LSEQ + l0 + t);
        B_s[t][n] = g_xdbl[row * XPROJN + DTRANK + n];
        C_s[t][n] = g_xdbl[row * XPROJN + DTRANK + DSTATE + n];
    }
    __syncthreads();

    float h[DSTATE];
    {
        const float* Hp = g_Hini + ((size_t)(cch * BATCH + b) * DINNER + e) * DSTATE;
        #pragma unroll
        for (int n = 0; n < DSTATE; n += 4) {
            float4 v = *reinterpret_cast<const float4*>(Hp + n);
            h[n] = v.x; h[n + 1] = v.y; h[n + 2] = v.z; h[n + 3] = v.w;
        }
    }

    #pragma unroll 4
    for (int t = 0; t < LC; t++) {
        float dt = dt_s[t][tid];
        float u  = u_s [t][tid];
        float du = dt * u;
        float y = 0.0f;
        #pragma unroll
        for (int n = 0; n < DSTATE; n++) {
            float dA = __expf(dt * Ar[n]);
            h[n] = fmaf(dA, h[n], du * B_s[t][n]);
            y = fmaf(h[n], C_s[t][n], y);
        }
        size_t row = (size_t)(b * LSEQ + l0 + t);
        float z = g_xz[row * 2 * DINNER + DINNER + e];
        float g = z / (1.0f + __expf(-z));
        split_store((y + u * Dp) * g, gA2h, gA2l, row * DINNER + e);
    }
}

// ---------------- launch ----------------------------------------------------
extern "C" void kernel_launch(void* const* d_in, const int* in_sizes, int n_in,
                              void* d_out, int out_size) {
    const float* x      = (const float*)d_in[0];
    const float* ln1_w  = (const float*)d_in[1];
    const float* ln1_b  = (const float*)d_in[2];
    const float* ln2_w  = (const float*)d_in[3];
    const float* ln2_b  = (const float*)d_in[4];
    const float* W_in   = (const float*)d_in[5];
    const float* conv_w = (const float*)d_in[6];
    const float* conv_b = (const float*)d_in[7];
    const float* W_xprj = (const float*)d_in[8];
    const float* W_dt   = (const float*)d_in[9];
    const float* b_dt   = (const float*)d_in[10];
    const float* A_log  = (const float*)d_in[11];
    const float* D_prm  = (const float*)d_in[12];
    const float* W_out  = (const float*)d_in[13];
    float* out = (float*)d_out;

    static int attr_done = 0;
    if (!attr_done) {
        cudaFuncSetAttribute(gemm_hmma<0>, cudaFuncAttributeMaxDynamicSharedMemorySize, GEMM_SMEM);
        cudaFuncSetAttribute(gemm_hmma<1>, cudaFuncAttributeMaxDynamicSharedMemorySize, GEMM_SMEM);
        cudaFuncSetAttribute(fused_mid_kernel, cudaFuncAttributeMaxDynamicSharedMemorySize, FUSED_SMEM);
        attr_done = 1;
    }

    // 0) weight transposes + splits (merged)
    tsplit_all<<<1536, 256>>>(W_in, W_out);
    // 1) LN1 -> split bf16 A1
    ln_kernel<0><<<NROWS, 128>>>(x, ln1_w, ln1_b, nullptr);
    // 2) g_xz = A1 @ W_in (HMMA, 2-stage pipeline)
    gemm_hmma<0><<<dim3(2 * DINNER / 128, NROWS / 128), 256, GEMM_SMEM>>>();
    // 3-5) fused conv+silu -> xproj -> dtproj
    fused_mid_kernel<<<NROWS / 32, 256, FUSED_SMEM>>>(conv_w, conv_b, W_xprj, W_dt, b_dt);
    // 6) chunked selective scan -> split bf16 A2
    scan1_kernel<<<dim3(DINNER / 128, BATCH, NC), 128>>>(A_log);
    scan2_kernel<<<dim3(DINNER / 16, BATCH), 256>>>(A_log);
    scan3_kernel<<<dim3(DINNER / 128, BATCH, NC), 128>>>(A_log, D_prm);
    // 7) g_yo = A2 @ W_out (HMMA, 2-stage pipeline)
    gemm_hmma<1><<<dim3(DMODEL / 128, NROWS / 128), 256, GEMM_SMEM>>>();
    // 8) out = LN2(x + g_yo)
    ln_kernel<1><<<NROWS, 128>>>(x, ln2_w, ln2_b, out);
}